// round 5
// baseline (speedup 1.0000x reference)
#include <cuda_runtime.h>
#include <cuda_fp16.h>
#include <stdint.h>

#define SQ 2048
#define DH 64
#define NH_ 16
#define NB_ 4
#define KT 32
#define NTILES (SQ/KT)
#define OUT_ELEMS (NB_*NH_*SQ*DH)
#define RSTRIDE 144

__device__ unsigned g_maskbits[(size_t)NB_ * SQ * (SQ / 32)];   // 2 MB
__device__ float    g_linv[(size_t)NB_ * NH_ * SQ];             // 512 KB

// pass A smem: Q hi/lo + K double buffer
#define SQH 0
#define SQL 18432
#define SKH(bf) (36864 + (bf)*9216)
#define SKL(bf) (SKH(bf) + 4608)
#define SMEM_A 55296
// pass B smem: V double buffer only
#define SVH(bf) ((bf)*9216)
#define SVL(bf) (SVH(bf) + 4608)
#define SMEM_B 18432

// ---------------- PTX helpers ----------------
__device__ __forceinline__ void ldsm4(uint32_t* r, uint32_t a) {
    asm volatile("ldmatrix.sync.aligned.m8n8.x4.shared.b16 {%0,%1,%2,%3}, [%4];"
                 : "=r"(r[0]), "=r"(r[1]), "=r"(r[2]), "=r"(r[3]) : "r"(a));
}
__device__ __forceinline__ void ldsm4t(uint32_t* r, uint32_t a) {
    asm volatile("ldmatrix.sync.aligned.m8n8.x4.trans.shared.b16 {%0,%1,%2,%3}, [%4];"
                 : "=r"(r[0]), "=r"(r[1]), "=r"(r[2]), "=r"(r[3]) : "r"(a));
}
__device__ __forceinline__ void mma16816(float* c, const uint32_t* a, const uint32_t* b) {
    asm volatile("mma.sync.aligned.m16n8k16.row.col.f32.f16.f16.f32 "
                 "{%0,%1,%2,%3}, {%4,%5,%6,%7}, {%8,%9}, {%0,%1,%2,%3};"
                 : "+f"(c[0]), "+f"(c[1]), "+f"(c[2]), "+f"(c[3])
                 : "r"(a[0]), "r"(a[1]), "r"(a[2]), "r"(a[3]), "r"(b[0]), "r"(b[1]));
}
__device__ __forceinline__ void splitpack(float x, float y, uint32_t& hi, uint32_t& lo) {
    __half hx = __float2half_rn(x), hy = __float2half_rn(y);
    float rx = x - __half2float(hx), ry = y - __half2float(hy);
    __half2 h = __halves2half2(hx, hy);
    __half2 l = __halves2half2(__float2half_rn(rx), __float2half_rn(ry));
    hi = *reinterpret_cast<uint32_t*>(&h);
    lo = *reinterpret_cast<uint32_t*>(&l);
}
__device__ __forceinline__ void sts_f4(char* sm, int offH, int offL, int lin, float4 x) {
    uint32_t h0, l0, h1, l1;
    splitpack(x.x, x.y, h0, l0);
    splitpack(x.z, x.w, h1, l1);
    uint32_t a = (uint32_t)(lin >> 4) * RSTRIDE + (uint32_t)(lin & 15) * 8;
    *reinterpret_cast<uint2*>(sm + offH + a) = make_uint2(h0, h1);
    *reinterpret_cast<uint2*>(sm + offL + a) = make_uint2(l0, l1);
}

// ---------------- mask bit-pack (warp ballot, coalesced) ----------------
__global__ void maskpack_kernel(const int* __restrict__ mask) {
    int gwarp = blockIdx.x * 8 + (threadIdx.x >> 5);
    int lane = threadIdx.x & 31;
    size_t base = (size_t)gwarp * 128;
    unsigned b0, b1, b2, b3;
    b0 = __ballot_sync(0xffffffffu, mask[base + lane] != 0);
    b1 = __ballot_sync(0xffffffffu, mask[base + 32 + lane] != 0);
    b2 = __ballot_sync(0xffffffffu, mask[base + 64 + lane] != 0);
    b3 = __ballot_sync(0xffffffffu, mask[base + 96 + lane] != 0);
    if (lane == 0)
        *reinterpret_cast<uint4*>(&g_maskbits[(size_t)gwarp * 4]) = make_uint4(b0, b1, b2, b3);
}

// ---------------- pass A: S = QK^T once; stash p = mask*exp(s); invl ----------------
__global__ __launch_bounds__(256, 2)
void sdpa_passA(const float* __restrict__ qg, const float* __restrict__ kg,
                float* __restrict__ outg)
{
    extern __shared__ char sm[];
    const uint32_t sb = (uint32_t)__cvta_generic_to_shared(sm);
    const int tid = threadIdx.x, warp = tid >> 5, lane = tid & 31;
    const int g = lane >> 2, t4 = lane & 3;
    const int qt = blockIdx.x, h = blockIdx.y, b = blockIdx.z;
    const int q0 = qt * 128;
    const size_t bh = (size_t)(b * NH_ + h);
    const float* qb = qg + (bh * SQ + (size_t)q0) * DH;
    const float* kb = kg + bh * SQ * DH;
    const int r0 = warp * 16 + g, r1 = r0 + 8;

    // Q -> smem f16 hi/lo (scale folded)
#pragma unroll
    for (int i = 0; i < 8; i++) {
        int lin = i * 256 + tid;
        float4 x = reinterpret_cast<const float4*>(qb)[lin];
        x.x *= 0.125f; x.y *= 0.125f; x.z *= 0.125f; x.w *= 0.125f;
        sts_f4(sm, SQH, SQL, lin, x);
    }
    // prologue: K tile 0
    float4 pk0 = reinterpret_cast<const float4*>(kb)[tid];
    float4 pk1 = reinterpret_cast<const float4*>(kb)[256 + tid];
    sts_f4(sm, SKH(0), SKL(0), tid, pk0);
    sts_f4(sm, SKH(0), SKL(0), 256 + tid, pk1);

    float lsum0 = 0.0f, lsum1 = 0.0f;

    const uint32_t qHaddr = sb + SQH + (uint32_t)(warp * 16 + (lane & 15)) * RSTRIDE
                          + (uint32_t)(lane >> 4) * 16;
    const uint32_t qLaddr = qHaddr + (SQL - SQH);
    const uint32_t kfoff = (uint32_t)(lane & 7) * RSTRIDE + (uint32_t)(lane >> 3) * 16;
    const unsigned* mw0 = &g_maskbits[((size_t)b * SQ + q0 + r0) * (SQ / 32)];
    const unsigned* mw1 = &g_maskbits[((size_t)b * SQ + q0 + r1) * (SQ / 32)];
    float* attnb = outg + (size_t)OUT_ELEMS + (bh * SQ + (size_t)q0) * SQ;
    float* at0 = attnb + (size_t)r0 * SQ;
    float* at1 = attnb + (size_t)r1 * SQ;

    for (int t = 0; t < NTILES; t++) {
        const int cur = t & 1;
        unsigned w0 = mw0[t], w1 = mw1[t];
        if (t + 1 < NTILES) {
            const float4* ks = reinterpret_cast<const float4*>(kb + (size_t)(t + 1) * KT * DH);
            pk0 = ks[tid]; pk1 = ks[256 + tid];
        }
        __syncthreads();

        float S[4][4];
#pragma unroll
        for (int ng = 0; ng < 4; ng++)
#pragma unroll
            for (int j = 0; j < 4; j++) S[ng][j] = 0.0f;

#pragma unroll
        for (int kp = 0; kp < 2; kp++) {
            uint32_t qh0[4], qh1[4], ql0[4], ql1[4];
            ldsm4(qh0, qHaddr + kp * 64);
            ldsm4(qh1, qHaddr + kp * 64 + 32);
            ldsm4(ql0, qLaddr + kp * 64);
            ldsm4(ql1, qLaddr + kp * 64 + 32);
#pragma unroll
            for (int ng = 0; ng < 4; ng++) {
                uint32_t kh[4], kl[4];
                ldsm4(kh, sb + SKH(cur) + (uint32_t)(ng * 8) * RSTRIDE + kp * 64 + kfoff);
                ldsm4(kl, sb + SKL(cur) + (uint32_t)(ng * 8) * RSTRIDE + kp * 64 + kfoff);
                mma16816(S[ng], qh0, kh + 0);
                mma16816(S[ng], qh0, kl + 0);
                mma16816(S[ng], ql0, kh + 0);
                mma16816(S[ng], qh1, kh + 2);
                mma16816(S[ng], qh1, kl + 2);
                mma16816(S[ng], ql1, kh + 2);
            }
        }

        // p = mask * exp(s); stash (streaming); accumulate row sums
#pragma unroll
        for (int ng = 0; ng < 4; ng++) {
            int j = 8 * ng + 2 * t4;
            float e00 = ((w0 >> j) & 1u)       ? __expf(S[ng][0]) : 0.0f;
            float e01 = ((w0 >> (j + 1)) & 1u) ? __expf(S[ng][1]) : 0.0f;
            float e10 = ((w1 >> j) & 1u)       ? __expf(S[ng][2]) : 0.0f;
            float e11 = ((w1 >> (j + 1)) & 1u) ? __expf(S[ng][3]) : 0.0f;
            lsum0 += e00 + e01;
            lsum1 += e10 + e11;
            int col = t * KT + j;
            __stcs(reinterpret_cast<float2*>(&at0[col]), make_float2(e00, e01));
            __stcs(reinterpret_cast<float2*>(&at1[col]), make_float2(e10, e11));
        }

        if (t + 1 < NTILES) {
            const int nxt = cur ^ 1;
            sts_f4(sm, SKH(nxt), SKL(nxt), tid, pk0);
            sts_f4(sm, SKH(nxt), SKL(nxt), 256 + tid, pk1);
        }
    }

    lsum0 += __shfl_xor_sync(0xffffffffu, lsum0, 1);
    lsum0 += __shfl_xor_sync(0xffffffffu, lsum0, 2);
    lsum1 += __shfl_xor_sync(0xffffffffu, lsum1, 1);
    lsum1 += __shfl_xor_sync(0xffffffffu, lsum1, 2);
    if (t4 == 0) {
        g_linv[bh * SQ + q0 + r0] = 1.0f / lsum0;
        g_linv[bh * SQ + q0 + r1] = 1.0f / lsum1;
    }
}

// ---------------- pass B: read p; attn = p*invl; O = (P V) * invl ----------------
__global__ __launch_bounds__(256, 2)
void sdpa_passB(const float* __restrict__ vg, float* __restrict__ outg)
{
    extern __shared__ char sm[];
    const uint32_t sb = (uint32_t)__cvta_generic_to_shared(sm);
    const int tid = threadIdx.x, warp = tid >> 5, lane = tid & 31;
    const int g = lane >> 2, t4 = lane & 3;
    const int qt = blockIdx.x, h = blockIdx.y, b = blockIdx.z;
    const int q0 = qt * 128;
    const size_t bh = (size_t)(b * NH_ + h);
    const float* vb = vg + bh * SQ * DH;
    const int r0 = warp * 16 + g, r1 = r0 + 8;

    const float invl0 = g_linv[bh * SQ + q0 + r0];
    const float invl1 = g_linv[bh * SQ + q0 + r1];

    // prologue: V tile 0
    float4 pv0 = reinterpret_cast<const float4*>(vb)[tid];
    float4 pv1 = reinterpret_cast<const float4*>(vb)[256 + tid];
    sts_f4(sm, SVH(0), SVL(0), tid, pv0);
    sts_f4(sm, SVH(0), SVL(0), 256 + tid, pv1);

    float O[8][4];
#pragma unroll
    for (int n = 0; n < 8; n++)
#pragma unroll
        for (int j = 0; j < 4; j++) O[n][j] = 0.0f;

    const uint32_t vfoff = (uint32_t)(8 * (lane >> 3) + (lane & 7)) * RSTRIDE;
    float* attnb = outg + (size_t)OUT_ELEMS + (bh * SQ + (size_t)q0) * SQ;
    float* at0 = attnb + (size_t)r0 * SQ;
    float* at1 = attnb + (size_t)r1 * SQ;

    for (int t = 0; t < NTILES; t++) {
        const int cur = t & 1;
        if (t + 1 < NTILES) {
            const float4* vs = reinterpret_cast<const float4*>(vb + (size_t)(t + 1) * KT * DH);
            pv0 = vs[tid]; pv1 = vs[256 + tid];
        }

        // read raw p (streaming), normalize for attn write, keep raw for MMA
        float S[4][4];
#pragma unroll
        for (int ng = 0; ng < 4; ng++) {
            int col = t * KT + 8 * ng + 2 * t4;
            float2 a0 = __ldcs(reinterpret_cast<const float2*>(&at0[col]));
            float2 a1 = __ldcs(reinterpret_cast<const float2*>(&at1[col]));
            S[ng][0] = a0.x; S[ng][1] = a0.y;
            S[ng][2] = a1.x; S[ng][3] = a1.y;
            __stcs(reinterpret_cast<float2*>(&at0[col]), make_float2(a0.x * invl0, a0.y * invl0));
            __stcs(reinterpret_cast<float2*>(&at1[col]), make_float2(a1.x * invl1, a1.y * invl1));
        }

        // raw p -> A-frags (hi/lo)
        uint32_t ahi[2][4], alo[2][4];
#pragma unroll
        for (int f = 0; f < 2; f++) {
            splitpack(S[2*f][0],   S[2*f][1],   ahi[f][0], alo[f][0]);
            splitpack(S[2*f][2],   S[2*f][3],   ahi[f][1], alo[f][1]);
            splitpack(S[2*f+1][0], S[2*f+1][1], ahi[f][2], alo[f][2]);
            splitpack(S[2*f+1][2], S[2*f+1][3], ahi[f][3], alo[f][3]);
        }

        __syncthreads();   // V buf[cur] ready
        // O += P V (3-term)
#pragma unroll
        for (int n = 0; n < 8; n++) {
            uint32_t bh4[4], bl4[4];
            ldsm4t(bh4, sb + SVH(cur) + vfoff + 16 * n);
            ldsm4t(bl4, sb + SVL(cur) + vfoff + 16 * n);
            mma16816(O[n], ahi[0], bh4 + 0);
            mma16816(O[n], ahi[0], bl4 + 0);
            mma16816(O[n], alo[0], bh4 + 0);
            mma16816(O[n], ahi[1], bh4 + 2);
            mma16816(O[n], ahi[1], bl4 + 2);
            mma16816(O[n], alo[1], bh4 + 2);
        }
        __syncthreads();   // done reading buf[cur]
        if (t + 1 < NTILES) {
            const int nxt = cur ^ 1;
            sts_f4(sm, SVH(nxt), SVL(nxt), tid, pv0);
            sts_f4(sm, SVH(nxt), SVL(nxt), 256 + tid, pv1);
        }
    }

    float* outb = outg + (bh * SQ + (size_t)q0) * DH;
#pragma unroll
    for (int n = 0; n < 8; n++) {
        int col = 8 * n + 2 * t4;
        *reinterpret_cast<float2*>(&outb[(size_t)r0 * DH + col]) =
            make_float2(O[n][0] * invl0, O[n][1] * invl0);
        *reinterpret_cast<float2*>(&outb[(size_t)r1 * DH + col]) =
            make_float2(O[n][2] * invl1, O[n][3] * invl1);
    }
}

extern "C" void kernel_launch(void* const* d_in, const int* in_sizes, int n_in,
                              void* d_out, int out_size) {
    const float* q   = (const float*)d_in[0];
    const float* k   = (const float*)d_in[1];
    const float* v   = (const float*)d_in[2];
    const int*   msk = (const int*)d_in[3];
    float* out = (float*)d_out;

    cudaFuncSetAttribute(sdpa_passA, cudaFuncAttributeMaxDynamicSharedMemorySize, SMEM_A);
    cudaFuncSetAttribute(sdpa_passB, cudaFuncAttributeMaxDynamicSharedMemorySize, SMEM_B);

    maskpack_kernel<<<(NB_ * SQ * SQ) / (128 * 8), 256>>>(msk);
    dim3 grid(SQ / 128, NH_, NB_);   // qt fastest: K/V slabs reused across q-tiles in L2
    sdpa_passA<<<grid, 256, SMEM_A>>>(q, k, out);
    sdpa_passB<<<grid, 256, SMEM_B>>>(v, out);
}

// round 6
// speedup vs baseline: 1.6095x; 1.6095x over previous
#include <cuda_runtime.h>
#include <cuda_fp16.h>
#include <stdint.h>

#define SQ 2048
#define DH 64
#define NH_ 16
#define NB_ 4
#define KT 32
#define NTILES (SQ/KT)
#define OUT_ELEMS (NB_*NH_*SQ*DH)
#define RSTRIDE 144

__device__ unsigned g_maskbits[(size_t)NB_ * SQ * (SQ / 32)];   // 2 MB
__device__ float    g_linv[(size_t)NB_ * NH_ * SQ];             // 512 KB

// pass0 smem: Q hi + K hi double buffer
#define P0_QH 0
#define P0_KH(bf) (18432 + (bf)*4608)
#define SMEM_0 27648
// pass1 smem: Q hi/lo + K hi double + V hi/lo double
#define SQH 0
#define SQL 18432
#define SKH(bf) (36864 + (bf)*4608)
#define SVH(bf) (46080 + (bf)*9216)
#define SVL(bf) (SVH(bf) + 4608)
#define SMEM_1 64512

// ---------------- PTX helpers ----------------
__device__ __forceinline__ void ldsm4(uint32_t* r, uint32_t a) {
    asm volatile("ldmatrix.sync.aligned.m8n8.x4.shared.b16 {%0,%1,%2,%3}, [%4];"
                 : "=r"(r[0]), "=r"(r[1]), "=r"(r[2]), "=r"(r[3]) : "r"(a));
}
__device__ __forceinline__ void ldsm4t(uint32_t* r, uint32_t a) {
    asm volatile("ldmatrix.sync.aligned.m8n8.x4.trans.shared.b16 {%0,%1,%2,%3}, [%4];"
                 : "=r"(r[0]), "=r"(r[1]), "=r"(r[2]), "=r"(r[3]) : "r"(a));
}
__device__ __forceinline__ void mma16816(float* c, const uint32_t* a, const uint32_t* b) {
    asm volatile("mma.sync.aligned.m16n8k16.row.col.f32.f16.f16.f32 "
                 "{%0,%1,%2,%3}, {%4,%5,%6,%7}, {%8,%9}, {%0,%1,%2,%3};"
                 : "+f"(c[0]), "+f"(c[1]), "+f"(c[2]), "+f"(c[3])
                 : "r"(a[0]), "r"(a[1]), "r"(a[2]), "r"(a[3]), "r"(b[0]), "r"(b[1]));
}
__device__ __forceinline__ void splitpack(float x, float y, uint32_t& hi, uint32_t& lo) {
    __half hx = __float2half_rn(x), hy = __float2half_rn(y);
    float rx = x - __half2float(hx), ry = y - __half2float(hy);
    __half2 h = __halves2half2(hx, hy);
    __half2 l = __halves2half2(__float2half_rn(rx), __float2half_rn(ry));
    hi = *reinterpret_cast<uint32_t*>(&h);
    lo = *reinterpret_cast<uint32_t*>(&l);
}
__device__ __forceinline__ uint32_t packh(float x, float y) {
    __half2 h = __halves2half2(__float2half_rn(x), __float2half_rn(y));
    return *reinterpret_cast<uint32_t*>(&h);
}
// hi+lo split store of 4 floats
__device__ __forceinline__ void sts_f4(char* sm, int offH, int offL, int lin, float4 x) {
    uint32_t h0, l0, h1, l1;
    splitpack(x.x, x.y, h0, l0);
    splitpack(x.z, x.w, h1, l1);
    uint32_t a = (uint32_t)(lin >> 4) * RSTRIDE + (uint32_t)(lin & 15) * 8;
    *reinterpret_cast<uint2*>(sm + offH + a) = make_uint2(h0, h1);
    *reinterpret_cast<uint2*>(sm + offL + a) = make_uint2(l0, l1);
}
// hi-only store of 4 floats
__device__ __forceinline__ void sts_f4h(char* sm, int offH, int lin, float4 x) {
    uint32_t a = (uint32_t)(lin >> 4) * RSTRIDE + (uint32_t)(lin & 15) * 8;
    *reinterpret_cast<uint2*>(sm + offH + a) = make_uint2(packh(x.x, x.y), packh(x.z, x.w));
}

// ---------------- mask bit-pack ----------------
__global__ void maskpack_kernel(const int* __restrict__ mask) {
    int gwarp = blockIdx.x * 8 + (threadIdx.x >> 5);
    int lane = threadIdx.x & 31;
    size_t base = (size_t)gwarp * 128;
    unsigned b0 = __ballot_sync(0xffffffffu, mask[base + lane] != 0);
    unsigned b1 = __ballot_sync(0xffffffffu, mask[base + 32 + lane] != 0);
    unsigned b2 = __ballot_sync(0xffffffffu, mask[base + 64 + lane] != 0);
    unsigned b3 = __ballot_sync(0xffffffffu, mask[base + 96 + lane] != 0);
    if (lane == 0)
        *reinterpret_cast<uint4*>(&g_maskbits[(size_t)gwarp * 4]) = make_uint4(b0, b1, b2, b3);
}

// ---------------- pass0: lsum via single-term fp16 QK ----------------
__global__ __launch_bounds__(256, 2)
void sdpa_pass0(const float* __restrict__ qg, const float* __restrict__ kg)
{
    extern __shared__ char sm[];
    const uint32_t sb = (uint32_t)__cvta_generic_to_shared(sm);
    const int tid = threadIdx.x, warp = tid >> 5, lane = tid & 31;
    const int g = lane >> 2, t4 = lane & 3;
    const int qt = blockIdx.x, h = blockIdx.y, b = blockIdx.z;
    const int q0 = qt * 128;
    const size_t bh = (size_t)(b * NH_ + h);
    const float* qb = qg + (bh * SQ + (size_t)q0) * DH;
    const float* kb = kg + bh * SQ * DH;
    const int r0 = warp * 16 + g, r1 = r0 + 8;

    // Q -> smem f16 hi only (scale folded)
#pragma unroll
    for (int i = 0; i < 8; i++) {
        int lin = i * 256 + tid;
        float4 x = reinterpret_cast<const float4*>(qb)[lin];
        x.x *= 0.125f; x.y *= 0.125f; x.z *= 0.125f; x.w *= 0.125f;
        sts_f4h(sm, P0_QH, lin, x);
    }
    float4 pk0 = reinterpret_cast<const float4*>(kb)[tid];
    float4 pk1 = reinterpret_cast<const float4*>(kb)[256 + tid];
    sts_f4h(sm, P0_KH(0), tid, pk0);
    sts_f4h(sm, P0_KH(0), 256 + tid, pk1);

    float lsum0 = 0.0f, lsum1 = 0.0f;
    const uint32_t qHaddr = sb + P0_QH + (uint32_t)(warp * 16 + (lane & 15)) * RSTRIDE
                          + (uint32_t)(lane >> 4) * 16;
    const uint32_t kfoff = (uint32_t)(lane & 7) * RSTRIDE + (uint32_t)(lane >> 3) * 16;
    const unsigned* mw0 = &g_maskbits[((size_t)b * SQ + q0 + r0) * (SQ / 32)];
    const unsigned* mw1 = &g_maskbits[((size_t)b * SQ + q0 + r1) * (SQ / 32)];

    for (int t = 0; t < NTILES; t++) {
        const int cur = t & 1;
        unsigned w0 = mw0[t], w1 = mw1[t];
        if (t + 1 < NTILES) {
            const float4* ks = reinterpret_cast<const float4*>(kb + (size_t)(t + 1) * KT * DH);
            pk0 = ks[tid]; pk1 = ks[256 + tid];
        }
        __syncthreads();

        float S[4][4];
#pragma unroll
        for (int ng = 0; ng < 4; ng++)
#pragma unroll
            for (int j = 0; j < 4; j++) S[ng][j] = 0.0f;

#pragma unroll
        for (int kp = 0; kp < 2; kp++) {
            uint32_t qh0[4], qh1[4];
            ldsm4(qh0, qHaddr + kp * 64);
            ldsm4(qh1, qHaddr + kp * 64 + 32);
#pragma unroll
            for (int ng = 0; ng < 4; ng++) {
                uint32_t kh[4];
                ldsm4(kh, sb + P0_KH(cur) + (uint32_t)(ng * 8) * RSTRIDE + kp * 64 + kfoff);
                mma16816(S[ng], qh0, kh + 0);
                mma16816(S[ng], qh1, kh + 2);
            }
        }

#pragma unroll
        for (int ng = 0; ng < 4; ng++) {
            int j = 8 * ng + 2 * t4;
            lsum0 += (((w0 >> j) & 1u)       ? __expf(S[ng][0]) : 0.0f)
                   + (((w0 >> (j + 1)) & 1u) ? __expf(S[ng][1]) : 0.0f);
            lsum1 += (((w1 >> j) & 1u)       ? __expf(S[ng][2]) : 0.0f)
                   + (((w1 >> (j + 1)) & 1u) ? __expf(S[ng][3]) : 0.0f);
        }

        if (t + 1 < NTILES) {
            const int nxt = cur ^ 1;
            sts_f4h(sm, P0_KH(nxt), tid, pk0);
            sts_f4h(sm, P0_KH(nxt), 256 + tid, pk1);
        }
    }

    lsum0 += __shfl_xor_sync(0xffffffffu, lsum0, 1);
    lsum0 += __shfl_xor_sync(0xffffffffu, lsum0, 2);
    lsum1 += __shfl_xor_sync(0xffffffffu, lsum1, 1);
    lsum1 += __shfl_xor_sync(0xffffffffu, lsum1, 2);
    if (t4 == 0) {
        g_linv[bh * SQ + q0 + r0] = 1.0f / lsum0;
        g_linv[bh * SQ + q0 + r1] = 1.0f / lsum1;
    }
}

// ---------------- pass1: QK 2-term, attn = p*invl, O += P V (3-term) ----------------
__global__ __launch_bounds__(256, 2)
void sdpa_pass1(const float* __restrict__ qg, const float* __restrict__ kg,
                const float* __restrict__ vg, float* __restrict__ outg)
{
    extern __shared__ char sm[];
    const uint32_t sb = (uint32_t)__cvta_generic_to_shared(sm);
    const int tid = threadIdx.x, warp = tid >> 5, lane = tid & 31;
    const int g = lane >> 2, t4 = lane & 3;
    const int qt = blockIdx.x, h = blockIdx.y, b = blockIdx.z;
    const int q0 = qt * 128;
    const size_t bh = (size_t)(b * NH_ + h);
    const float* qb = qg + (bh * SQ + (size_t)q0) * DH;
    const float* kb = kg + bh * SQ * DH;
    const float* vb = vg + bh * SQ * DH;
    const int r0 = warp * 16 + g, r1 = r0 + 8;

    const float invl0 = g_linv[bh * SQ + q0 + r0];
    const float invl1 = g_linv[bh * SQ + q0 + r1];

    // Q -> smem f16 hi/lo (scale folded)
#pragma unroll
    for (int i = 0; i < 8; i++) {
        int lin = i * 256 + tid;
        float4 x = reinterpret_cast<const float4*>(qb)[lin];
        x.x *= 0.125f; x.y *= 0.125f; x.z *= 0.125f; x.w *= 0.125f;
        sts_f4(sm, SQH, SQL, lin, x);
    }
    // prologue tile 0: K hi, V hi/lo
    float4 pk0 = reinterpret_cast<const float4*>(kb)[tid];
    float4 pk1 = reinterpret_cast<const float4*>(kb)[256 + tid];
    float4 pv0 = reinterpret_cast<const float4*>(vb)[tid];
    float4 pv1 = reinterpret_cast<const float4*>(vb)[256 + tid];
    sts_f4h(sm, SKH(0), tid, pk0);
    sts_f4h(sm, SKH(0), 256 + tid, pk1);
    sts_f4(sm, SVH(0), SVL(0), tid, pv0);
    sts_f4(sm, SVH(0), SVL(0), 256 + tid, pv1);

    float O[8][4];
#pragma unroll
    for (int n = 0; n < 8; n++)
#pragma unroll
        for (int j = 0; j < 4; j++) O[n][j] = 0.0f;

    const uint32_t qHaddr = sb + SQH + (uint32_t)(warp * 16 + (lane & 15)) * RSTRIDE
                          + (uint32_t)(lane >> 4) * 16;
    const uint32_t qLaddr = qHaddr + (SQL - SQH);
    const uint32_t kfoff = (uint32_t)(lane & 7) * RSTRIDE + (uint32_t)(lane >> 3) * 16;
    const uint32_t vfoff = (uint32_t)(8 * (lane >> 3) + (lane & 7)) * RSTRIDE;
    const unsigned* mw0 = &g_maskbits[((size_t)b * SQ + q0 + r0) * (SQ / 32)];
    const unsigned* mw1 = &g_maskbits[((size_t)b * SQ + q0 + r1) * (SQ / 32)];
    float* attnb = outg + (size_t)OUT_ELEMS + (bh * SQ + (size_t)q0) * SQ;
    float* at0 = attnb + (size_t)r0 * SQ;
    float* at1 = attnb + (size_t)r1 * SQ;

    for (int t = 0; t < NTILES; t++) {
        const int cur = t & 1;
        unsigned w0 = mw0[t], w1 = mw1[t];
        if (t + 1 < NTILES) {
            const float4* ks = reinterpret_cast<const float4*>(kb + (size_t)(t + 1) * KT * DH);
            const float4* vs = reinterpret_cast<const float4*>(vb + (size_t)(t + 1) * KT * DH);
            pk0 = ks[tid]; pk1 = ks[256 + tid];
            pv0 = vs[tid]; pv1 = vs[256 + tid];
        }
        __syncthreads();

        // ---- S = Q K^T, 2-term: (qh+ql) * kh ----
        float S[4][4];
#pragma unroll
        for (int ng = 0; ng < 4; ng++)
#pragma unroll
            for (int j = 0; j < 4; j++) S[ng][j] = 0.0f;

#pragma unroll
        for (int kp = 0; kp < 2; kp++) {
            uint32_t qh0[4], qh1[4], ql0[4], ql1[4];
            ldsm4(qh0, qHaddr + kp * 64);
            ldsm4(qh1, qHaddr + kp * 64 + 32);
            ldsm4(ql0, qLaddr + kp * 64);
            ldsm4(ql1, qLaddr + kp * 64 + 32);
#pragma unroll
            for (int ng = 0; ng < 4; ng++) {
                uint32_t kh[4];
                ldsm4(kh, sb + SKH(cur) + (uint32_t)(ng * 8) * RSTRIDE + kp * 64 + kfoff);
                mma16816(S[ng], qh0, kh + 0);
                mma16816(S[ng], ql0, kh + 0);
                mma16816(S[ng], qh1, kh + 2);
                mma16816(S[ng], ql1, kh + 2);
            }
        }

        // ---- p = mask*exp(s)*invl; write attn; keep for PV ----
#pragma unroll
        for (int ng = 0; ng < 4; ng++) {
            int j = 8 * ng + 2 * t4;
            float e00 = ((w0 >> j) & 1u)       ? __expf(S[ng][0]) * invl0 : 0.0f;
            float e01 = ((w0 >> (j + 1)) & 1u) ? __expf(S[ng][1]) * invl0 : 0.0f;
            float e10 = ((w1 >> j) & 1u)       ? __expf(S[ng][2]) * invl1 : 0.0f;
            float e11 = ((w1 >> (j + 1)) & 1u) ? __expf(S[ng][3]) * invl1 : 0.0f;
            S[ng][0] = e00; S[ng][1] = e01; S[ng][2] = e10; S[ng][3] = e11;
            int col = t * KT + j;
            __stcs(reinterpret_cast<float2*>(&at0[col]), make_float2(e00, e01));
            __stcs(reinterpret_cast<float2*>(&at1[col]), make_float2(e10, e11));
        }

        // p -> A-frags (hi/lo)
        uint32_t ahi[2][4], alo[2][4];
#pragma unroll
        for (int f = 0; f < 2; f++) {
            splitpack(S[2*f][0],   S[2*f][1],   ahi[f][0], alo[f][0]);
            splitpack(S[2*f][2],   S[2*f][3],   ahi[f][1], alo[f][1]);
            splitpack(S[2*f+1][0], S[2*f+1][1], ahi[f][2], alo[f][2]);
            splitpack(S[2*f+1][2], S[2*f+1][3], ahi[f][3], alo[f][3]);
        }

        // ---- O += P V (3-term) ----
#pragma unroll
        for (int n = 0; n < 8; n++) {
            uint32_t bh4[4], bl4[4];
            ldsm4t(bh4, sb + SVH(cur) + vfoff + 16 * n);
            ldsm4t(bl4, sb + SVL(cur) + vfoff + 16 * n);
            mma16816(O[n], ahi[0], bh4 + 0);
            mma16816(O[n], ahi[0], bl4 + 0);
            mma16816(O[n], alo[0], bh4 + 0);
            mma16816(O[n], ahi[1], bh4 + 2);
            mma16816(O[n], ahi[1], bl4 + 2);
            mma16816(O[n], alo[1], bh4 + 2);
        }

        if (t + 1 < NTILES) {
            const int nxt = cur ^ 1;
            sts_f4h(sm, SKH(nxt), tid, pk0);
            sts_f4h(sm, SKH(nxt), 256 + tid, pk1);
            sts_f4(sm, SVH(nxt), SVL(nxt), tid, pv0);
            sts_f4(sm, SVH(nxt), SVL(nxt), 256 + tid, pv1);
        }
    }

    float* outb = outg + (bh * SQ + (size_t)q0) * DH;
#pragma unroll
    for (int n = 0; n < 8; n++) {
        int col = 8 * n + 2 * t4;
        *reinterpret_cast<float2*>(&outb[(size_t)r0 * DH + col]) = make_float2(O[n][0], O[n][1]);
        *reinterpret_cast<float2*>(&outb[(size_t)r1 * DH + col]) = make_float2(O[n][2], O[n][3]);
    }
}

extern "C" void kernel_launch(void* const* d_in, const int* in_sizes, int n_in,
                              void* d_out, int out_size) {
    const float* q   = (const float*)d_in[0];
    const float* k   = (const float*)d_in[1];
    const float* v   = (const float*)d_in[2];
    const int*   msk = (const int*)d_in[3];
    float* out = (float*)d_out;

    cudaFuncSetAttribute(sdpa_pass0, cudaFuncAttributeMaxDynamicSharedMemorySize, SMEM_0);
    cudaFuncSetAttribute(sdpa_pass1, cudaFuncAttributeMaxDynamicSharedMemorySize, SMEM_1);

    maskpack_kernel<<<(NB_ * SQ * SQ) / (128 * 8), 256>>>(msk);
    dim3 grid(SQ / 128, NH_, NB_);   // qt fastest: K/V slabs reused across q-tiles in L2
    sdpa_pass0<<<grid, 256, SMEM_0>>>(q, k);
    sdpa_pass1<<<grid, 256, SMEM_1>>>(q, k, v, out);
}

// round 7
// speedup vs baseline: 1.8409x; 1.1438x over previous
#include <cuda_runtime.h>
#include <cuda_fp16.h>
#include <stdint.h>

#define SQ 2048
#define DH 64
#define NH_ 16
#define NB_ 4
#define KT 32
#define NTILES (SQ/KT)
#define OUT_ELEMS (NB_*NH_*SQ*DH)
#define RSTRIDE 144
#define QSCALE 0.18033688011112042f   // 0.125 * log2(e); exp(s) = exp2(S)

__device__ unsigned g_maskbits[(size_t)NB_ * SQ * (SQ / 32)];   // 2 MB
__device__ float    g_linv[(size_t)NB_ * NH_ * SQ];             // 512 KB

// pass0 smem: Q hi + K hi double buffer
#define P0_QH 0
#define P0_KH(bf) (18432 + (bf)*4608)
#define SMEM_0 27648
// pass1 smem: Q hi/lo + K hi double + V hi double
#define SQH 0
#define SQL 18432
#define SKH(bf) (36864 + (bf)*4608)
#define SVH(bf) (46080 + (bf)*4608)
#define SMEM_1 55296

// ---------------- PTX helpers ----------------
__device__ __forceinline__ void ldsm4(uint32_t* r, uint32_t a) {
    asm volatile("ldmatrix.sync.aligned.m8n8.x4.shared.b16 {%0,%1,%2,%3}, [%4];"
                 : "=r"(r[0]), "=r"(r[1]), "=r"(r[2]), "=r"(r[3]) : "r"(a));
}
__device__ __forceinline__ void ldsm4t(uint32_t* r, uint32_t a) {
    asm volatile("ldmatrix.sync.aligned.m8n8.x4.trans.shared.b16 {%0,%1,%2,%3}, [%4];"
                 : "=r"(r[0]), "=r"(r[1]), "=r"(r[2]), "=r"(r[3]) : "r"(a));
}
__device__ __forceinline__ void mma16816(float* c, const uint32_t* a, const uint32_t* b) {
    asm volatile("mma.sync.aligned.m16n8k16.row.col.f32.f16.f16.f32 "
                 "{%0,%1,%2,%3}, {%4,%5,%6,%7}, {%8,%9}, {%0,%1,%2,%3};"
                 : "+f"(c[0]), "+f"(c[1]), "+f"(c[2]), "+f"(c[3])
                 : "r"(a[0]), "r"(a[1]), "r"(a[2]), "r"(a[3]), "r"(b[0]), "r"(b[1]));
}
__device__ __forceinline__ void splitpack(float x, float y, uint32_t& hi, uint32_t& lo) {
    __half hx = __float2half_rn(x), hy = __float2half_rn(y);
    float rx = x - __half2float(hx), ry = y - __half2float(hy);
    __half2 h = __halves2half2(hx, hy);
    __half2 l = __halves2half2(__float2half_rn(rx), __float2half_rn(ry));
    hi = *reinterpret_cast<uint32_t*>(&h);
    lo = *reinterpret_cast<uint32_t*>(&l);
}
__device__ __forceinline__ uint32_t packh(float x, float y) {
    __half2 h = __halves2half2(__float2half_rn(x), __float2half_rn(y));
    return *reinterpret_cast<uint32_t*>(&h);
}
__device__ __forceinline__ void sts_f4(char* sm, int offH, int offL, int lin, float4 x) {
    uint32_t h0, l0, h1, l1;
    splitpack(x.x, x.y, h0, l0);
    splitpack(x.z, x.w, h1, l1);
    uint32_t a = (uint32_t)(lin >> 4) * RSTRIDE + (uint32_t)(lin & 15) * 8;
    *reinterpret_cast<uint2*>(sm + offH + a) = make_uint2(h0, h1);
    *reinterpret_cast<uint2*>(sm + offL + a) = make_uint2(l0, l1);
}
__device__ __forceinline__ void sts_f4h(char* sm, int offH, int lin, float4 x) {
    uint32_t a = (uint32_t)(lin >> 4) * RSTRIDE + (uint32_t)(lin & 15) * 8;
    *reinterpret_cast<uint2*>(sm + offH + a) = make_uint2(packh(x.x, x.y), packh(x.z, x.w));
}

// ---------------- mask bit-pack ----------------
__global__ void maskpack_kernel(const int* __restrict__ mask) {
    int gwarp = blockIdx.x * 8 + (threadIdx.x >> 5);
    int lane = threadIdx.x & 31;
    size_t base = (size_t)gwarp * 128;
    unsigned b0 = __ballot_sync(0xffffffffu, mask[base + lane] != 0);
    unsigned b1 = __ballot_sync(0xffffffffu, mask[base + 32 + lane] != 0);
    unsigned b2 = __ballot_sync(0xffffffffu, mask[base + 64 + lane] != 0);
    unsigned b3 = __ballot_sync(0xffffffffu, mask[base + 96 + lane] != 0);
    if (lane == 0)
        *reinterpret_cast<uint4*>(&g_maskbits[(size_t)gwarp * 4]) = make_uint4(b0, b1, b2, b3);
}

// ---------------- pass0: lsum via single-term fp16 QK ----------------
__global__ __launch_bounds__(256, 2)
void sdpa_pass0(const float* __restrict__ qg, const float* __restrict__ kg)
{
    extern __shared__ char sm[];
    const uint32_t sb = (uint32_t)__cvta_generic_to_shared(sm);
    const int tid = threadIdx.x, warp = tid >> 5, lane = tid & 31;
    const int g = lane >> 2, t4 = lane & 3;
    const int qt = blockIdx.x, h = blockIdx.y, b = blockIdx.z;
    const int q0 = qt * 128;
    const size_t bh = (size_t)(b * NH_ + h);
    const float* qb = qg + (bh * SQ + (size_t)q0) * DH;
    const float* kb = kg + bh * SQ * DH;
    const int r0 = warp * 16 + g, r1 = r0 + 8;

#pragma unroll
    for (int i = 0; i < 8; i++) {
        int lin = i * 256 + tid;
        float4 x = reinterpret_cast<const float4*>(qb)[lin];
        x.x *= QSCALE; x.y *= QSCALE; x.z *= QSCALE; x.w *= QSCALE;
        sts_f4h(sm, P0_QH, lin, x);
    }
    float4 pk0 = reinterpret_cast<const float4*>(kb)[tid];
    float4 pk1 = reinterpret_cast<const float4*>(kb)[256 + tid];
    sts_f4h(sm, P0_KH(0), tid, pk0);
    sts_f4h(sm, P0_KH(0), 256 + tid, pk1);

    float lsum0 = 0.0f, lsum1 = 0.0f;
    const uint32_t qHaddr = sb + P0_QH + (uint32_t)(warp * 16 + (lane & 15)) * RSTRIDE
                          + (uint32_t)(lane >> 4) * 16;
    const uint32_t kfoff = (uint32_t)(lane & 7) * RSTRIDE + (uint32_t)(lane >> 3) * 16;
    const unsigned* mw0 = &g_maskbits[((size_t)b * SQ + q0 + r0) * (SQ / 32)];
    const unsigned* mw1 = &g_maskbits[((size_t)b * SQ + q0 + r1) * (SQ / 32)];

    for (int t = 0; t < NTILES; t++) {
        const int cur = t & 1;
        unsigned w0 = mw0[t], w1 = mw1[t];
        if (t + 1 < NTILES) {
            const float4* ks = reinterpret_cast<const float4*>(kb + (size_t)(t + 1) * KT * DH);
            pk0 = ks[tid]; pk1 = ks[256 + tid];
        }
        __syncthreads();

        float S[4][4];
#pragma unroll
        for (int ng = 0; ng < 4; ng++)
#pragma unroll
            for (int j = 0; j < 4; j++) S[ng][j] = 0.0f;

#pragma unroll
        for (int kp = 0; kp < 2; kp++) {
            uint32_t qh0[4], qh1[4];
            ldsm4(qh0, qHaddr + kp * 64);
            ldsm4(qh1, qHaddr + kp * 64 + 32);
#pragma unroll
            for (int ng = 0; ng < 4; ng++) {
                uint32_t kh[4];
                ldsm4(kh, sb + P0_KH(cur) + (uint32_t)(ng * 8) * RSTRIDE + kp * 64 + kfoff);
                mma16816(S[ng], qh0, kh + 0);
                mma16816(S[ng], qh1, kh + 2);
            }
        }

#pragma unroll
        for (int ng = 0; ng < 4; ng++) {
            int j = 8 * ng + 2 * t4;
            lsum0 += (((w0 >> j) & 1u)       ? exp2f(S[ng][0]) : 0.0f)
                   + (((w0 >> (j + 1)) & 1u) ? exp2f(S[ng][1]) : 0.0f);
            lsum1 += (((w1 >> j) & 1u)       ? exp2f(S[ng][2]) : 0.0f)
                   + (((w1 >> (j + 1)) & 1u) ? exp2f(S[ng][3]) : 0.0f);
        }

        if (t + 1 < NTILES) {
            const int nxt = cur ^ 1;
            sts_f4h(sm, P0_KH(nxt), tid, pk0);
            sts_f4h(sm, P0_KH(nxt), 256 + tid, pk1);
        }
    }

    lsum0 += __shfl_xor_sync(0xffffffffu, lsum0, 1);
    lsum0 += __shfl_xor_sync(0xffffffffu, lsum0, 2);
    lsum1 += __shfl_xor_sync(0xffffffffu, lsum1, 1);
    lsum1 += __shfl_xor_sync(0xffffffffu, lsum1, 2);
    if (t4 == 0) {
        g_linv[bh * SQ + q0 + r0] = 1.0f / lsum0;
        g_linv[bh * SQ + q0 + r1] = 1.0f / lsum1;
    }
}

// ---------------- pass1: QK 2-term; attn = p*invl; O += P V_hi (2-term) ----------------
__global__ __launch_bounds__(256, 2)
void sdpa_pass1(const float* __restrict__ qg, const float* __restrict__ kg,
                const float* __restrict__ vg, float* __restrict__ outg)
{
    extern __shared__ char sm[];
    const uint32_t sb = (uint32_t)__cvta_generic_to_shared(sm);
    const int tid = threadIdx.x, warp = tid >> 5, lane = tid & 31;
    const int g = lane >> 2, t4 = lane & 3;
    const int qt = blockIdx.x, h = blockIdx.y, b = blockIdx.z;
    const int q0 = qt * 128;
    const size_t bh = (size_t)(b * NH_ + h);
    const float* qb = qg + (bh * SQ + (size_t)q0) * DH;
    const float* kb = kg + bh * SQ * DH;
    const float* vb = vg + bh * SQ * DH;
    const int r0 = warp * 16 + g, r1 = r0 + 8;

    const float invl0 = g_linv[bh * SQ + q0 + r0];
    const float invl1 = g_linv[bh * SQ + q0 + r1];

#pragma unroll
    for (int i = 0; i < 8; i++) {
        int lin = i * 256 + tid;
        float4 x = reinterpret_cast<const float4*>(qb)[lin];
        x.x *= QSCALE; x.y *= QSCALE; x.z *= QSCALE; x.w *= QSCALE;
        sts_f4(sm, SQH, SQL, lin, x);
    }
    float4 pk0 = reinterpret_cast<const float4*>(kb)[tid];
    float4 pk1 = reinterpret_cast<const float4*>(kb)[256 + tid];
    float4 pv0 = reinterpret_cast<const float4*>(vb)[tid];
    float4 pv1 = reinterpret_cast<const float4*>(vb)[256 + tid];
    sts_f4h(sm, SKH(0), tid, pk0);
    sts_f4h(sm, SKH(0), 256 + tid, pk1);
    sts_f4h(sm, SVH(0), tid, pv0);
    sts_f4h(sm, SVH(0), 256 + tid, pv1);

    float O[8][4];
#pragma unroll
    for (int n = 0; n < 8; n++)
#pragma unroll
        for (int j = 0; j < 4; j++) O[n][j] = 0.0f;

    const uint32_t qHaddr = sb + SQH + (uint32_t)(warp * 16 + (lane & 15)) * RSTRIDE
                          + (uint32_t)(lane >> 4) * 16;
    const uint32_t qLaddr = qHaddr + (SQL - SQH);
    const uint32_t kfoff = (uint32_t)(lane & 7) * RSTRIDE + (uint32_t)(lane >> 3) * 16;
    const uint32_t vfoff = (uint32_t)(8 * (lane >> 3) + (lane & 7)) * RSTRIDE;
    const unsigned* mw0 = &g_maskbits[((size_t)b * SQ + q0 + r0) * (SQ / 32)];
    const unsigned* mw1 = &g_maskbits[((size_t)b * SQ + q0 + r1) * (SQ / 32)];
    float* attnb = outg + (size_t)OUT_ELEMS + (bh * SQ + (size_t)q0) * SQ;
    float* at0 = attnb + (size_t)r0 * SQ;
    float* at1 = attnb + (size_t)r1 * SQ;

    for (int t = 0; t < NTILES; t++) {
        const int cur = t & 1;
        unsigned w0 = mw0[t], w1 = mw1[t];
        if (t + 1 < NTILES) {
            const float4* ks = reinterpret_cast<const float4*>(kb + (size_t)(t + 1) * KT * DH);
            const float4* vs = reinterpret_cast<const float4*>(vb + (size_t)(t + 1) * KT * DH);
            pk0 = ks[tid]; pk1 = ks[256 + tid];
            pv0 = vs[tid]; pv1 = vs[256 + tid];
        }
        __syncthreads();

        // ---- S = Q K^T, 2-term: (qh+ql) * kh ----
        float S[4][4];
#pragma unroll
        for (int ng = 0; ng < 4; ng++)
#pragma unroll
            for (int j = 0; j < 4; j++) S[ng][j] = 0.0f;

#pragma unroll
        for (int kp = 0; kp < 2; kp++) {
            uint32_t qh0[4], qh1[4], ql0[4], ql1[4];
            ldsm4(qh0, qHaddr + kp * 64);
            ldsm4(qh1, qHaddr + kp * 64 + 32);
            ldsm4(ql0, qLaddr + kp * 64);
            ldsm4(ql1, qLaddr + kp * 64 + 32);
#pragma unroll
            for (int ng = 0; ng < 4; ng++) {
                uint32_t kh[4];
                ldsm4(kh, sb + SKH(cur) + (uint32_t)(ng * 8) * RSTRIDE + kp * 64 + kfoff);
                mma16816(S[ng], qh0, kh + 0);
                mma16816(S[ng], ql0, kh + 0);
                mma16816(S[ng], qh1, kh + 2);
                mma16816(S[ng], ql1, kh + 2);
            }
        }

        // ---- p = mask*exp2(S)*invl; write attn; keep for PV ----
#pragma unroll
        for (int ng = 0; ng < 4; ng++) {
            int j = 8 * ng + 2 * t4;
            float e00 = ((w0 >> j) & 1u)       ? exp2f(S[ng][0]) * invl0 : 0.0f;
            float e01 = ((w0 >> (j + 1)) & 1u) ? exp2f(S[ng][1]) * invl0 : 0.0f;
            float e10 = ((w1 >> j) & 1u)       ? exp2f(S[ng][2]) * invl1 : 0.0f;
            float e11 = ((w1 >> (j + 1)) & 1u) ? exp2f(S[ng][3]) * invl1 : 0.0f;
            S[ng][0] = e00; S[ng][1] = e01; S[ng][2] = e10; S[ng][3] = e11;
            int col = t * KT + j;
            __stcs(reinterpret_cast<float2*>(&at0[col]), make_float2(e00, e01));
            __stcs(reinterpret_cast<float2*>(&at1[col]), make_float2(e10, e11));
        }

        // p -> A-frags (hi/lo)
        uint32_t ahi[2][4], alo[2][4];
#pragma unroll
        for (int f = 0; f < 2; f++) {
            splitpack(S[2*f][0],   S[2*f][1],   ahi[f][0], alo[f][0]);
            splitpack(S[2*f][2],   S[2*f][3],   ahi[f][1], alo[f][1]);
            splitpack(S[2*f+1][0], S[2*f+1][1], ahi[f][2], alo[f][2]);
            splitpack(S[2*f+1][2], S[2*f+1][3], ahi[f][3], alo[f][3]);
        }

        // ---- O += P V_hi (2-term: (ph+pl)·vh) ----
#pragma unroll
        for (int n = 0; n < 8; n++) {
            uint32_t bh4[4];
            ldsm4t(bh4, sb + SVH(cur) + vfoff + 16 * n);
            mma16816(O[n], ahi[0], bh4 + 0);
            mma16816(O[n], alo[0], bh4 + 0);
            mma16816(O[n], ahi[1], bh4 + 2);
            mma16816(O[n], alo[1], bh4 + 2);
        }

        if (t + 1 < NTILES) {
            const int nxt = cur ^ 1;
            sts_f4h(sm, SKH(nxt), tid, pk0);
            sts_f4h(sm, SKH(nxt), 256 + tid, pk1);
            sts_f4h(sm, SVH(nxt), tid, pv0);
            sts_f4h(sm, SVH(nxt), 256 + tid, pv1);
        }
    }

    float* outb = outg + (bh * SQ + (size_t)q0) * DH;
#pragma unroll
    for (int n = 0; n < 8; n++) {
        int col = 8 * n + 2 * t4;
        *reinterpret_cast<float2*>(&outb[(size_t)r0 * DH + col]) = make_float2(O[n][0], O[n][1]);
        *reinterpret_cast<float2*>(&outb[(size_t)r1 * DH + col]) = make_float2(O[n][2], O[n][3]);
    }
}

extern "C" void kernel_launch(void* const* d_in, const int* in_sizes, int n_in,
                              void* d_out, int out_size) {
    const float* q   = (const float*)d_in[0];
    const float* k   = (const float*)d_in[1];
    const float* v   = (const float*)d_in[2];
    const int*   msk = (const int*)d_in[3];
    float* out = (float*)d_out;

    cudaFuncSetAttribute(sdpa_pass0, cudaFuncAttributeMaxDynamicSharedMemorySize, SMEM_0);
    cudaFuncSetAttribute(sdpa_pass1, cudaFuncAttributeMaxDynamicSharedMemorySize, SMEM_1);

    maskpack_kernel<<<(NB_ * SQ * SQ) / (128 * 8), 256>>>(msk);
    dim3 grid(SQ / 128, NH_, NB_);
    sdpa_pass0<<<grid, 256, SMEM_0>>>(q, k);
    sdpa_pass1<<<grid, 256, SMEM_1>>>(q, k, v, out);
}

// round 8
// speedup vs baseline: 1.9867x; 1.0792x over previous
#include <cuda_runtime.h>
#include <cuda_fp16.h>
#include <stdint.h>

#define SQ 2048
#define DH 64
#define NH_ 16
#define NB_ 4
#define KT 32
#define NTILES (SQ/KT)
#define OUT_ELEMS (NB_*NH_*SQ*DH)
#define RSTRIDE 144
#define QSCALE 0.18033688011112042f   // 0.125 * log2(e); exp(s) = exp2(S)

__device__ unsigned g_maskbits[(size_t)NB_ * SQ * (SQ / 32)];   // 2 MB
__device__ float    g_linv[(size_t)NB_ * NH_ * SQ];             // 512 KB

// pass0 smem: Q hi + K hi double buffer
#define P0_QH 0
#define P0_KH(bf) (18432 + (bf)*4608)
#define SMEM_0 27648
// pass1 smem: Q hi + K hi double + V hi double
#define SQH 0
#define SKH(bf) (18432 + (bf)*4608)
#define SVH(bf) (27648 + (bf)*4608)
#define SMEM_1 36864

// ---------------- PTX helpers ----------------
__device__ __forceinline__ void ldsm4(uint32_t* r, uint32_t a) {
    asm volatile("ldmatrix.sync.aligned.m8n8.x4.shared.b16 {%0,%1,%2,%3}, [%4];"
                 : "=r"(r[0]), "=r"(r[1]), "=r"(r[2]), "=r"(r[3]) : "r"(a));
}
__device__ __forceinline__ void ldsm4t(uint32_t* r, uint32_t a) {
    asm volatile("ldmatrix.sync.aligned.m8n8.x4.trans.shared.b16 {%0,%1,%2,%3}, [%4];"
                 : "=r"(r[0]), "=r"(r[1]), "=r"(r[2]), "=r"(r[3]) : "r"(a));
}
__device__ __forceinline__ void mma16816(float* c, const uint32_t* a, const uint32_t* b) {
    asm volatile("mma.sync.aligned.m16n8k16.row.col.f32.f16.f16.f32 "
                 "{%0,%1,%2,%3}, {%4,%5,%6,%7}, {%8,%9}, {%0,%1,%2,%3};"
                 : "+f"(c[0]), "+f"(c[1]), "+f"(c[2]), "+f"(c[3])
                 : "r"(a[0]), "r"(a[1]), "r"(a[2]), "r"(a[3]), "r"(b[0]), "r"(b[1]));
}
__device__ __forceinline__ uint32_t packh(float x, float y) {
    __half2 h = __halves2half2(__float2half_rn(x), __float2half_rn(y));
    return *reinterpret_cast<uint32_t*>(&h);
}
__device__ __forceinline__ void sts_f4h(char* sm, int offH, int lin, float4 x) {
    uint32_t a = (uint32_t)(lin >> 4) * RSTRIDE + (uint32_t)(lin & 15) * 8;
    *reinterpret_cast<uint2*>(sm + offH + a) = make_uint2(packh(x.x, x.y), packh(x.z, x.w));
}

// ---------------- mask bit-pack ----------------
__global__ void maskpack_kernel(const int* __restrict__ mask) {
    int gwarp = blockIdx.x * 8 + (threadIdx.x >> 5);
    int lane = threadIdx.x & 31;
    size_t base = (size_t)gwarp * 128;
    unsigned b0 = __ballot_sync(0xffffffffu, mask[base + lane] != 0);
    unsigned b1 = __ballot_sync(0xffffffffu, mask[base + 32 + lane] != 0);
    unsigned b2 = __ballot_sync(0xffffffffu, mask[base + 64 + lane] != 0);
    unsigned b3 = __ballot_sync(0xffffffffu, mask[base + 96 + lane] != 0);
    if (lane == 0)
        *reinterpret_cast<uint4*>(&g_maskbits[(size_t)gwarp * 4]) = make_uint4(b0, b1, b2, b3);
}

// ---------------- pass0: lsum via single-term fp16 QK ----------------
__global__ __launch_bounds__(256, 2)
void sdpa_pass0(const float* __restrict__ qg, const float* __restrict__ kg)
{
    extern __shared__ char sm[];
    const uint32_t sb = (uint32_t)__cvta_generic_to_shared(sm);
    const int tid = threadIdx.x, warp = tid >> 5, lane = tid & 31;
    const int g = lane >> 2, t4 = lane & 3;
    const int qt = blockIdx.x, h = blockIdx.y, b = blockIdx.z;
    const int q0 = qt * 128;
    const size_t bh = (size_t)(b * NH_ + h);
    const float* qb = qg + (bh * SQ + (size_t)q0) * DH;
    const float* kb = kg + bh * SQ * DH;
    const int r0 = warp * 16 + g, r1 = r0 + 8;

#pragma unroll
    for (int i = 0; i < 8; i++) {
        int lin = i * 256 + tid;
        float4 x = reinterpret_cast<const float4*>(qb)[lin];
        x.x *= QSCALE; x.y *= QSCALE; x.z *= QSCALE; x.w *= QSCALE;
        sts_f4h(sm, P0_QH, lin, x);
    }
    float4 pk0 = reinterpret_cast<const float4*>(kb)[tid];
    float4 pk1 = reinterpret_cast<const float4*>(kb)[256 + tid];
    sts_f4h(sm, P0_KH(0), tid, pk0);
    sts_f4h(sm, P0_KH(0), 256 + tid, pk1);

    float lsum0 = 0.0f, lsum1 = 0.0f;
    const uint32_t qHaddr = sb + P0_QH + (uint32_t)(warp * 16 + (lane & 15)) * RSTRIDE
                          + (uint32_t)(lane >> 4) * 16;
    const uint32_t kfoff = (uint32_t)(lane & 7) * RSTRIDE + (uint32_t)(lane >> 3) * 16;
    const unsigned* mw0 = &g_maskbits[((size_t)b * SQ + q0 + r0) * (SQ / 32)];
    const unsigned* mw1 = &g_maskbits[((size_t)b * SQ + q0 + r1) * (SQ / 32)];

    for (int t = 0; t < NTILES; t++) {
        const int cur = t & 1;
        unsigned w0 = mw0[t], w1 = mw1[t];
        if (t + 1 < NTILES) {
            const float4* ks = reinterpret_cast<const float4*>(kb + (size_t)(t + 1) * KT * DH);
            pk0 = ks[tid]; pk1 = ks[256 + tid];
        }
        __syncthreads();

        float S[4][4];
#pragma unroll
        for (int ng = 0; ng < 4; ng++)
#pragma unroll
            for (int j = 0; j < 4; j++) S[ng][j] = 0.0f;

#pragma unroll
        for (int kp = 0; kp < 2; kp++) {
            uint32_t qh0[4], qh1[4];
            ldsm4(qh0, qHaddr + kp * 64);
            ldsm4(qh1, qHaddr + kp * 64 + 32);
#pragma unroll
            for (int ng = 0; ng < 4; ng++) {
                uint32_t kh[4];
                ldsm4(kh, sb + P0_KH(cur) + (uint32_t)(ng * 8) * RSTRIDE + kp * 64 + kfoff);
                mma16816(S[ng], qh0, kh + 0);
                mma16816(S[ng], qh1, kh + 2);
            }
        }

#pragma unroll
        for (int ng = 0; ng < 4; ng++) {
            int j = 8 * ng + 2 * t4;
            lsum0 += (((w0 >> j) & 1u)       ? exp2f(S[ng][0]) : 0.0f)
                   + (((w0 >> (j + 1)) & 1u) ? exp2f(S[ng][1]) : 0.0f);
            lsum1 += (((w1 >> j) & 1u)       ? exp2f(S[ng][2]) : 0.0f)
                   + (((w1 >> (j + 1)) & 1u) ? exp2f(S[ng][3]) : 0.0f);
        }

        if (t + 1 < NTILES) {
            const int nxt = cur ^ 1;
            sts_f4h(sm, P0_KH(nxt), tid, pk0);
            sts_f4h(sm, P0_KH(nxt), 256 + tid, pk1);
        }
    }

    lsum0 += __shfl_xor_sync(0xffffffffu, lsum0, 1);
    lsum0 += __shfl_xor_sync(0xffffffffu, lsum0, 2);
    lsum1 += __shfl_xor_sync(0xffffffffu, lsum1, 1);
    lsum1 += __shfl_xor_sync(0xffffffffu, lsum1, 2);
    if (t4 == 0) {
        g_linv[bh * SQ + q0 + r0] = 1.0f / lsum0;
        g_linv[bh * SQ + q0 + r1] = 1.0f / lsum1;
    }
}

// ---------------- pass1: QK 1-term (identical to pass0); attn = p*invl; O += P_hi V_hi ----------------
__global__ __launch_bounds__(256, 2)
void sdpa_pass1(const float* __restrict__ qg, const float* __restrict__ kg,
                const float* __restrict__ vg, float* __restrict__ outg)
{
    extern __shared__ char sm[];
    const uint32_t sb = (uint32_t)__cvta_generic_to_shared(sm);
    const int tid = threadIdx.x, warp = tid >> 5, lane = tid & 31;
    const int g = lane >> 2, t4 = lane & 3;
    const int qt = blockIdx.x, h = blockIdx.y, b = blockIdx.z;
    const int q0 = qt * 128;
    const size_t bh = (size_t)(b * NH_ + h);
    const float* qb = qg + (bh * SQ + (size_t)q0) * DH;
    const float* kb = kg + bh * SQ * DH;
    const float* vb = vg + bh * SQ * DH;
    const int r0 = warp * 16 + g, r1 = r0 + 8;

    const float invl0 = g_linv[bh * SQ + q0 + r0];
    const float invl1 = g_linv[bh * SQ + q0 + r1];

#pragma unroll
    for (int i = 0; i < 8; i++) {
        int lin = i * 256 + tid;
        float4 x = reinterpret_cast<const float4*>(qb)[lin];
        x.x *= QSCALE; x.y *= QSCALE; x.z *= QSCALE; x.w *= QSCALE;
        sts_f4h(sm, SQH, lin, x);
    }
    float4 pk0 = reinterpret_cast<const float4*>(kb)[tid];
    float4 pk1 = reinterpret_cast<const float4*>(kb)[256 + tid];
    float4 pv0 = reinterpret_cast<const float4*>(vb)[tid];
    float4 pv1 = reinterpret_cast<const float4*>(vb)[256 + tid];
    sts_f4h(sm, SKH(0), tid, pk0);
    sts_f4h(sm, SKH(0), 256 + tid, pk1);
    sts_f4h(sm, SVH(0), tid, pv0);
    sts_f4h(sm, SVH(0), 256 + tid, pv1);

    float O[8][4];
#pragma unroll
    for (int n = 0; n < 8; n++)
#pragma unroll
        for (int j = 0; j < 4; j++) O[n][j] = 0.0f;

    const uint32_t qHaddr = sb + SQH + (uint32_t)(warp * 16 + (lane & 15)) * RSTRIDE
                          + (uint32_t)(lane >> 4) * 16;
    const uint32_t kfoff = (uint32_t)(lane & 7) * RSTRIDE + (uint32_t)(lane >> 3) * 16;
    const uint32_t vfoff = (uint32_t)(8 * (lane >> 3) + (lane & 7)) * RSTRIDE;
    const unsigned* mw0 = &g_maskbits[((size_t)b * SQ + q0 + r0) * (SQ / 32)];
    const unsigned* mw1 = &g_maskbits[((size_t)b * SQ + q0 + r1) * (SQ / 32)];
    float* attnb = outg + (size_t)OUT_ELEMS + (bh * SQ + (size_t)q0) * SQ;
    float* at0 = attnb + (size_t)r0 * SQ;
    float* at1 = attnb + (size_t)r1 * SQ;

    for (int t = 0; t < NTILES; t++) {
        const int cur = t & 1;
        unsigned w0 = mw0[t], w1 = mw1[t];
        if (t + 1 < NTILES) {
            const float4* ks = reinterpret_cast<const float4*>(kb + (size_t)(t + 1) * KT * DH);
            const float4* vs = reinterpret_cast<const float4*>(vb + (size_t)(t + 1) * KT * DH);
            pk0 = ks[tid]; pk1 = ks[256 + tid];
            pv0 = vs[tid]; pv1 = vs[256 + tid];
        }
        __syncthreads();

        // ---- S = Q_hi K_hi^T (identical arithmetic to pass0) ----
        float S[4][4];
#pragma unroll
        for (int ng = 0; ng < 4; ng++)
#pragma unroll
            for (int j = 0; j < 4; j++) S[ng][j] = 0.0f;

#pragma unroll
        for (int kp = 0; kp < 2; kp++) {
            uint32_t qh0[4], qh1[4];
            ldsm4(qh0, qHaddr + kp * 64);
            ldsm4(qh1, qHaddr + kp * 64 + 32);
#pragma unroll
            for (int ng = 0; ng < 4; ng++) {
                uint32_t kh[4];
                ldsm4(kh, sb + SKH(cur) + (uint32_t)(ng * 8) * RSTRIDE + kp * 64 + kfoff);
                mma16816(S[ng], qh0, kh + 0);
                mma16816(S[ng], qh1, kh + 2);
            }
        }

        // ---- p = mask*exp2(S)*invl; write attn; keep for PV ----
#pragma unroll
        for (int ng = 0; ng < 4; ng++) {
            int j = 8 * ng + 2 * t4;
            float e00 = ((w0 >> j) & 1u)       ? exp2f(S[ng][0]) * invl0 : 0.0f;
            float e01 = ((w0 >> (j + 1)) & 1u) ? exp2f(S[ng][1]) * invl0 : 0.0f;
            float e10 = ((w1 >> j) & 1u)       ? exp2f(S[ng][2]) * invl1 : 0.0f;
            float e11 = ((w1 >> (j + 1)) & 1u) ? exp2f(S[ng][3]) * invl1 : 0.0f;
            S[ng][0] = e00; S[ng][1] = e01; S[ng][2] = e10; S[ng][3] = e11;
            int col = t * KT + j;
            __stcs(reinterpret_cast<float2*>(&at0[col]), make_float2(e00, e01));
            __stcs(reinterpret_cast<float2*>(&at1[col]), make_float2(e10, e11));
        }

        // p -> A-frags (hi only)
        uint32_t ahi[2][4];
#pragma unroll
        for (int f = 0; f < 2; f++) {
            ahi[f][0] = packh(S[2*f][0],   S[2*f][1]);
            ahi[f][1] = packh(S[2*f][2],   S[2*f][3]);
            ahi[f][2] = packh(S[2*f+1][0], S[2*f+1][1]);
            ahi[f][3] = packh(S[2*f+1][2], S[2*f+1][3]);
        }

        // ---- O += P_hi V_hi ----
#pragma unroll
        for (int n = 0; n < 8; n++) {
            uint32_t bh4[4];
            ldsm4t(bh4, sb + SVH(cur) + vfoff + 16 * n);
            mma16816(O[n], ahi[0], bh4 + 0);
            mma16816(O[n], ahi[1], bh4 + 2);
        }

        if (t + 1 < NTILES) {
            const int nxt = cur ^ 1;
            sts_f4h(sm, SKH(nxt), tid, pk0);
            sts_f4h(sm, SKH(nxt), 256 + tid, pk1);
            sts_f4h(sm, SVH(nxt), tid, pv0);
            sts_f4h(sm, SVH(nxt), 256 + tid, pv1);
        }
    }

    float* outb = outg + (bh * SQ + (size_t)q0) * DH;
#pragma unroll
    for (int n = 0; n < 8; n++) {
        int col = 8 * n + 2 * t4;
        *reinterpret_cast<float2*>(&outb[(size_t)r0 * DH + col]) = make_float2(O[n][0], O[n][1]);
        *reinterpret_cast<float2*>(&outb[(size_t)r1 * DH + col]) = make_float2(O[n][2], O[n][3]);
    }
}

extern "C" void kernel_launch(void* const* d_in, const int* in_sizes, int n_in,
                              void* d_out, int out_size) {
    const float* q   = (const float*)d_in[0];
    const float* k   = (const float*)d_in[1];
    const float* v   = (const float*)d_in[2];
    const int*   msk = (const int*)d_in[3];
    float* out = (float*)d_out;

    cudaFuncSetAttribute(sdpa_pass0, cudaFuncAttributeMaxDynamicSharedMemorySize, SMEM_0);
    cudaFuncSetAttribute(sdpa_pass1, cudaFuncAttributeMaxDynamicSharedMemorySize, SMEM_1);

    maskpack_kernel<<<(NB_ * SQ * SQ) / (128 * 8), 256>>>(msk);
    dim3 grid(SQ / 128, NH_, NB_);
    sdpa_pass0<<<grid, 256, SMEM_0>>>(q, k);
    sdpa_pass1<<<grid, 256, SMEM_1>>>(q, k, v, out);
}